// round 2
// baseline (speedup 1.0000x reference)
#include <cuda_runtime.h>

#define P    8192
#define NB   4
#define NPTS 2048
#define Dd   3
#define Cc   64
#define HH   512
#define MT   16
#define TPB  256
#define GRID (P/MT)
#define EPSBN 1e-4f

// ---------------- scratch (static __device__, no allocations) ----------------
__device__ float g_Gc0[P*HH];
__device__ float g_Gc1[P*HH];
__device__ float g_Gc2[P*HH];
__device__ float g_Gc3[P*Dd];
__device__ float g_Bc0[P*HH];
__device__ float g_Bc1[P*HH];
__device__ float g_Bc2[P*HH];
__device__ float g_Bc3[P*Dd];
__device__ float g_xs[P*Dd];   // current state x
__device__ float g_xe[P*Dd];   // stage input
__device__ float g_ax[P*Dd];   // RK4 dx accumulator
__device__ float g_lp[P];      // logp
__device__ float g_al[P];      // RK4 dlogp accumulator
// folded tangent weights: V1[d][j*HH+k] = W1[j,k]*W0[k,d] ; V2[d][j*HH+k] = W2[j,k]*W3[d,j]
__device__ float g_V1[3][HH*HH];
__device__ float g_V2[3][HH*HH];

__device__ __forceinline__ float sigf(float z) { return 1.f/(1.f+__expf(-z)); }

__device__ __forceinline__ unsigned long long ffma2(unsigned long long a,
                                                    unsigned long long b,
                                                    unsigned long long c) {
    unsigned long long d;
    asm("fma.rn.f32x2 %0, %1, %2, %3;" : "=l"(d) : "l"(a), "l"(b), "l"(c));
    return d;
}
__device__ __forceinline__ float upack(unsigned long long v) {
    float2 f = *reinterpret_cast<float2*>(&v);
    return f.x + f.y;
}

// ------------- fold kernel: build V1, V2 (once per launch) -------------
__global__ void __launch_bounds__(TPB) fold_kernel(
    const float* __restrict__ W0, const float* __restrict__ W1,
    const float* __restrict__ W2, const float* __restrict__ W3)
{
    int idx = blockIdx.x*TPB + threadIdx.x;   // over HH*HH
    float w1 = W1[idx], w2 = W2[idx];
    int k = idx & (HH-1);
    int j = idx >> 9;
    #pragma unroll
    for (int d = 0; d < 3; ++d) {
        g_V1[d][idx] = w1 * W0[k*3+d];
        g_V2[d][idx] = w2 * W3[d*HH+j];
    }
}

// ------------- precompute: bn1, lp init, Gc/Bc = hyper nets applied to c -------------
__global__ void __launch_bounds__(TPB) pre_kernel(
    const float* __restrict__ x, const float* __restrict__ c,
    const float* __restrict__ m1, const float* __restrict__ v1,
    const float* __restrict__ lg1, const float* __restrict__ be1,
    const float* __restrict__ Wg0, const float* __restrict__ bg0, const float* __restrict__ Wb0,
    const float* __restrict__ Wg1, const float* __restrict__ bg1, const float* __restrict__ Wb1,
    const float* __restrict__ Wg2, const float* __restrict__ bg2, const float* __restrict__ Wb2,
    const float* __restrict__ Wg3, const float* __restrict__ bg3, const float* __restrict__ Wb3)
{
    __shared__ float cs[MT][Cc];
    int tid = threadIdx.x;
    int base = blockIdx.x * MT;
    for (int i = tid; i < MT*Cc; i += TPB) cs[i>>6][i&63] = c[base*Cc + i];
    if (tid < MT*Dd) {
        int m = tid/Dd, d = tid - m*Dd, p = base+m;
        float val = (x[p*Dd+d] - m1[d]) * __expf(lg1[d]) * rsqrtf(v1[d]+EPSBN) + be1[d];
        g_xs[p*Dd+d] = val; g_xe[p*Dd+d] = val;
    }
    if (tid >= 64 && tid < 64+MT) {
        int m = tid-64, p = base+m;
        float ld = 0.f;
        #pragma unroll
        for (int d = 0; d < Dd; ++d) ld += lg1[d] - 0.5f*logf(v1[d]+EPSBN);
        g_lp[p] = -ld;
    }
    __syncthreads();

    const float* WGs[3] = {Wg0, Wg1, Wg2};
    const float* BGs[3] = {bg0, bg1, bg2};
    const float* WBs[3] = {Wb0, Wb1, Wb2};
    float* GCs[3] = {g_Gc0, g_Gc1, g_Gc2};
    float* BCs[3] = {g_Bc0, g_Bc1, g_Bc2};
    #pragma unroll
    for (int l = 0; l < 3; ++l) {
        const float* Wg = WGs[l]; const float* Wb = WBs[l];
        #pragma unroll
        for (int s = 0; s < 2; ++s) {
            int j = tid + s*TPB;
            float ag[MT], ab[MT];
            #pragma unroll
            for (int m = 0; m < MT; ++m) { ag[m]=0.f; ab[m]=0.f; }
            const float* wgr = Wg + j*(Cc+1) + 1;
            const float* wbr = Wb + j*(Cc+1) + 1;
            for (int q = 0; q < Cc; ++q) {
                float a = wgr[q], b = wbr[q];
                #pragma unroll
                for (int m = 0; m < MT; ++m) { ag[m] += a*cs[m][q]; ab[m] += b*cs[m][q]; }
            }
            float bgj = BGs[l][j];
            float* Gc = GCs[l]; float* Bc = BCs[l];
            for (int m = 0; m < MT; ++m) {
                int p = base+m;
                Gc[p*HH+j] = ag[m]+bgj; Bc[p*HH+j] = ab[m];
            }
        }
    }
    if (tid < Dd) {
        int j = tid;
        float ag[MT], ab[MT];
        #pragma unroll
        for (int m = 0; m < MT; ++m) { ag[m]=0.f; ab[m]=0.f; }
        const float* wgr = Wg3 + j*(Cc+1) + 1;
        const float* wbr = Wb3 + j*(Cc+1) + 1;
        for (int q = 0; q < Cc; ++q) {
            float a = wgr[q], b = wbr[q];
            #pragma unroll
            for (int m = 0; m < MT; ++m) { ag[m] += a*cs[m][q]; ab[m] += b*cs[m][q]; }
        }
        for (int m = 0; m < MT; ++m) {
            int p = base+m;
            g_Gc3[p*Dd+j] = ag[m]+bg3[j]; g_Bc3[p*Dd+j] = ab[m];
        }
    }
}

// ------------- GEMM micro-kernel (FFMA2, k-paired): s0/s1 = cols tid, tid+256 -------------
__device__ __forceinline__ void gemmF(const float* __restrict__ Wv,
                                      const float* __restrict__ in_s,
                                      float* s0, float* s1, int tid)
{
    unsigned long long a0[MT], a1[MT];
    #pragma unroll
    for (int m = 0; m < MT; ++m) { a0[m] = 0ull; a1[m] = 0ull; }
    const ulonglong2* wp0 = reinterpret_cast<const ulonglong2*>(Wv + (size_t)tid*HH);
    const ulonglong2* wp1 = reinterpret_cast<const ulonglong2*>(Wv + (size_t)(tid+TPB)*HH);
    const ulonglong2* ip  = reinterpret_cast<const ulonglong2*>(in_s);
    #pragma unroll 2
    for (int k4 = 0; k4 < HH/4; ++k4) {
        ulonglong2 wa = wp0[k4];
        ulonglong2 wb = wp1[k4];
        #pragma unroll
        for (int m = 0; m < MT; ++m) {
            ulonglong2 iv = ip[m*(HH/4) + k4];
            a0[m] = ffma2(iv.x, wa.x, a0[m]);
            a0[m] = ffma2(iv.y, wa.y, a0[m]);
            a1[m] = ffma2(iv.x, wb.x, a1[m]);
            a1[m] = ffma2(iv.y, wb.y, a1[m]);
        }
    }
    #pragma unroll
    for (int m = 0; m < MT; ++m) { s0[m] = upack(a0[m]); s1[m] = upack(a1[m]); }
}

// ------------- one dynamics eval (primal + 3 JVPs) + fused RK4 stage update -------------
__global__ void __launch_bounds__(TPB) eval_kernel(
    const float* __restrict__ W0, const float* __restrict__ b0,
    const float* __restrict__ Wg0, const float* __restrict__ Wb0,
    const float* __restrict__ W1, const float* __restrict__ b1,
    const float* __restrict__ Wg1, const float* __restrict__ Wb1,
    const float* __restrict__ W2, const float* __restrict__ b2,
    const float* __restrict__ Wg2, const float* __restrict__ Wb2,
    const float* __restrict__ W3, const float* __restrict__ b3,
    const float* __restrict__ Wg3, const float* __restrict__ Wb3,
    const float* __restrict__ sqrtT, int stage, float tc)
{
    extern __shared__ float sm[];
    float* h1    = sm;                   // MT*HH  (tanh out, later q1)
    float* h2    = sm + 1*MT*HH;         // MT*HH  (tanh out, later q2)
    float* h3    = sm + 2*MT*HH;         // MT*HH  (tanh out, later q3)
    float* ub    = sm + 3*MT*HH;         // MT*HH  tangent intermediate
    float* pdbuf = sm + 4*MT*HH;         // MT*TPB partial divergence
    float* p2    = pdbuf + MT*TPB;       // TPB
    float* xin   = p2 + TPB;             // MT*3
    float* sdx   = xin + MT*Dd;          // MT*3
    float* sdiv  = sdx + MT*Dd;          // MT

    int tid = threadIdx.x;
    int base = blockIdx.x*MT;
    float sT = sqrtT[0];
    float dt = sT*sT*(1.f/3.f);
    float t  = tc*dt;
    float s0[MT], s1[MT];

    if (tid < MT*Dd) xin[tid] = g_xe[base*Dd + tid];
    if (tid < MT) sdiv[tid] = 0.f;
    __syncthreads();

    // primal L0: 3 -> 512
    #pragma unroll
    for (int s = 0; s < 2; ++s) {
        int j = tid + s*TPB;
        float wa = W0[j*3], wb = W0[j*3+1], wc = W0[j*3+2];
        float bj = b0[j];
        float wgt = Wg0[j*65], wbt = Wb0[j*65];
        for (int m = 0; m < MT; ++m) {
            int p = base+m;
            float z = xin[m*3]*wa + xin[m*3+1]*wb + xin[m*3+2]*wc + bj;
            float g = sigf(t*wgt + g_Gc0[(size_t)p*HH+j]);
            float bbv = t*wbt + g_Bc0[(size_t)p*HH+j];
            h1[m*HH+j] = tanhf(z*g + bbv);
        }
    }
    __syncthreads();

    // primal L1: 512 -> 512
    gemmF(W1, h1, s0, s1, tid);
    #pragma unroll
    for (int s = 0; s < 2; ++s) {
        int j = tid + s*TPB;
        float bj = b1[j], wgt = Wg1[j*65], wbt = Wb1[j*65];
        const float* sv = s ? s1 : s0;
        for (int m = 0; m < MT; ++m) {
            int p = base+m;
            float z = sv[m] + bj;
            float g = sigf(t*wgt + g_Gc1[(size_t)p*HH+j]);
            float bbv = t*wbt + g_Bc1[(size_t)p*HH+j];
            h2[m*HH+j] = tanhf(z*g + bbv);
        }
    }
    __syncthreads();

    // primal L2: 512 -> 512
    gemmF(W2, h2, s0, s1, tid);
    #pragma unroll
    for (int s = 0; s < 2; ++s) {
        int j = tid + s*TPB;
        float bj = b2[j], wgt = Wg2[j*65], wbt = Wb2[j*65];
        const float* sv = s ? s1 : s0;
        for (int m = 0; m < MT; ++m) {
            int p = base+m;
            float z = sv[m] + bj;
            float g = sigf(t*wgt + g_Gc2[(size_t)p*HH+j]);
            float bbv = t*wbt + g_Bc2[(size_t)p*HH+j];
            h3[m*HH+j] = tanhf(z*g + bbv);
        }
    }
    __syncthreads();

    // primal out: dx = (h3 @ W3^T + b3)*g3 + bb3  (warp per 2 points, 3 dims each)
    {
        int warp = tid>>5, lane = tid&31;
        for (int q = 0; q < 6; ++q) {
            int m = warp*2 + q/3;
            int d = q - (q/3)*3;
            float ssum = 0.f;
            const float* hr = h3 + m*HH;
            const float* wr = W3 + d*HH;
            for (int k = lane; k < HH; k += 32) ssum += hr[k]*wr[k];
            #pragma unroll
            for (int off = 16; off > 0; off >>= 1) ssum += __shfl_xor_sync(0xffffffffu, ssum, off);
            if (lane == 0) {
                int p = base+m;
                float z = ssum + b3[d];
                float g = sigf(t*Wg3[d*65] + g_Gc3[p*3+d]);
                float bbv = t*Wb3[d*65] + g_Bc3[p*3+d];
                sdx[m*3+d] = z*g + bbv;
            }
        }
    }
    __syncthreads();

    // in-place transform h_i -> q_i = (1-h_i^2)*gate_i  (reused by all 3 tangent dirs)
    #pragma unroll
    for (int s = 0; s < 2; ++s) {
        int j = tid + s*TPB;
        float wg0 = Wg0[j*65], wg1 = Wg1[j*65], wg2 = Wg2[j*65];
        for (int m = 0; m < MT; ++m) {
            int p = base+m;
            float hv1 = h1[m*HH+j];
            h1[m*HH+j] = (1.f-hv1*hv1)*sigf(t*wg0 + g_Gc0[(size_t)p*HH+j]);
            float hv2 = h2[m*HH+j];
            h2[m*HH+j] = (1.f-hv2*hv2)*sigf(t*wg1 + g_Gc1[(size_t)p*HH+j]);
            float hv3 = h3[m*HH+j];
            h3[m*HH+j] = (1.f-hv3*hv3)*sigf(t*wg2 + g_Gc2[(size_t)p*HH+j]);
        }
    }
    __syncthreads();

    // tangent dirs with folded weights:
    //   ub = q2 .* (V1d @ q1) ;  div_d = sum_j q3[j] * (V2d @ ub)[j] ; sdiv += g3d * div_d
    for (int dir = 0; dir < 3; ++dir) {
        gemmF(&g_V1[dir][0], h1, s0, s1, tid);
        #pragma unroll
        for (int m = 0; m < MT; ++m) {
            ub[m*HH + tid]       = h2[m*HH + tid]       * s0[m];
            ub[m*HH + tid + TPB] = h2[m*HH + tid + TPB] * s1[m];
        }
        __syncthreads();

        gemmF(&g_V2[dir][0], ub, s0, s1, tid);
        #pragma unroll
        for (int m = 0; m < MT; ++m) {
            float pd = s0[m]*h3[m*HH + tid] + s1[m]*h3[m*HH + tid + TPB];
            pdbuf[m*TPB + tid] = pd;
        }
        __syncthreads();

        // reduce 256 partials per m -> 16 -> 1
        {
            int m = tid >> 4, l16 = tid & 15;
            float s = 0.f;
            #pragma unroll
            for (int w = 0; w < 16; ++w) s += pdbuf[m*TPB + l16 + w*16];
            p2[tid] = s;
        }
        __syncthreads();
        if (tid < MT) {
            float tt = 0.f;
            #pragma unroll
            for (int i = 0; i < 16; ++i) tt += p2[tid*16 + i];
            int p = base + tid;
            float g = sigf(t*Wg3[dir*65] + g_Gc3[p*3+dir]);
            sdiv[tid] += tt * g;
        }
        __syncthreads();
    }

    // fused RK4 stage update
    if (tid < MT) {
        int m = tid, p = base+m;
        float kl = -sdiv[m];
        float kx0 = sdx[m*3], kx1 = sdx[m*3+1], kx2 = sdx[m*3+2];
        if (stage == 0) {
            g_al[p] = kl;
            g_ax[p*3]=kx0; g_ax[p*3+1]=kx1; g_ax[p*3+2]=kx2;
            g_xe[p*3]  = g_xs[p*3]  + 0.5f*dt*kx0;
            g_xe[p*3+1]= g_xs[p*3+1]+ 0.5f*dt*kx1;
            g_xe[p*3+2]= g_xs[p*3+2]+ 0.5f*dt*kx2;
        } else if (stage == 1) {
            g_al[p] += 2.f*kl;
            g_ax[p*3]+=2.f*kx0; g_ax[p*3+1]+=2.f*kx1; g_ax[p*3+2]+=2.f*kx2;
            g_xe[p*3]  = g_xs[p*3]  + 0.5f*dt*kx0;
            g_xe[p*3+1]= g_xs[p*3+1]+ 0.5f*dt*kx1;
            g_xe[p*3+2]= g_xs[p*3+2]+ 0.5f*dt*kx2;
        } else if (stage == 2) {
            g_al[p] += 2.f*kl;
            g_ax[p*3]+=2.f*kx0; g_ax[p*3+1]+=2.f*kx1; g_ax[p*3+2]+=2.f*kx2;
            g_xe[p*3]  = g_xs[p*3]  + dt*kx0;
            g_xe[p*3+1]= g_xs[p*3+1]+ dt*kx1;
            g_xe[p*3+2]= g_xs[p*3+2]+ dt*kx2;
        } else {
            float c6 = dt*(1.f/6.f);
            g_lp[p] += c6*(g_al[p] + kl);
            float n0 = g_xs[p*3]   + c6*(g_ax[p*3]   + kx0);
            float n1 = g_xs[p*3+1] + c6*(g_ax[p*3+1] + kx1);
            float n2 = g_xs[p*3+2] + c6*(g_ax[p*3+2] + kx2);
            g_xs[p*3]=n0;   g_xe[p*3]=n0;
            g_xs[p*3+1]=n1; g_xe[p*3+1]=n1;
            g_xs[p*3+2]=n2; g_xe[p*3+2]=n2;
        }
    }
}

// ------------- bn2 + per-batch logp reduction + output -------------
__global__ void __launch_bounds__(TPB) final_kernel(
    const float* __restrict__ m2, const float* __restrict__ v2,
    const float* __restrict__ lg2, const float* __restrict__ be2,
    float* __restrict__ out)
{
    __shared__ float red[TPB];
    int b = blockIdx.x, tid = threadIdx.x;
    float sc[3], mn[3], bt[3];
    float ld2 = 0.f;
    #pragma unroll
    for (int d = 0; d < 3; ++d) {
        sc[d] = __expf(lg2[d]) * rsqrtf(v2[d]+EPSBN);
        mn[d] = m2[d]; bt[d] = be2[d];
        ld2 += lg2[d] - 0.5f*logf(v2[d]+EPSBN);
    }
    float part = 0.f;
    for (int n = tid; n < NPTS; n += TPB) {
        int p = b*NPTS + n;
        #pragma unroll
        for (int d = 0; d < 3; ++d)
            out[p*3+d] = (g_xs[p*3+d]-mn[d])*sc[d] + bt[d];
        part += g_lp[p] - ld2;
    }
    red[tid] = part;
    __syncthreads();
    for (int off = TPB/2; off > 0; off >>= 1) {
        if (tid < off) red[tid] += red[tid+off];
        __syncthreads();
    }
    if (tid == 0) out[P*3 + b] = red[0];
}

// ---------------- launch ----------------
extern "C" void kernel_launch(void* const* d_in, const int* in_sizes, int n_in,
                              void* d_out, int out_size)
{
    const float* x    = (const float*)d_in[0];
    const float* c    = (const float*)d_in[1];
    const float* bn1m = (const float*)d_in[2];
    const float* bn1v = (const float*)d_in[3];
    const float* bn1g = (const float*)d_in[4];
    const float* bn1b = (const float*)d_in[5];
    const float* bn2m = (const float*)d_in[6];
    const float* bn2v = (const float*)d_in[7];
    const float* bn2g = (const float*)d_in[8];
    const float* bn2b = (const float*)d_in[9];
    const float* sqT  = (const float*)d_in[10];
    const float *W[4], *bb[4], *Wg[4], *bg[4], *Wb[4];
    for (int i = 0; i < 4; ++i) {
        W[i]  = (const float*)d_in[11+5*i];
        bb[i] = (const float*)d_in[12+5*i];
        Wg[i] = (const float*)d_in[13+5*i];
        bg[i] = (const float*)d_in[14+5*i];
        Wb[i] = (const float*)d_in[15+5*i];
    }

    int smem = (4*MT*HH + MT*TPB + TPB + MT*Dd*2 + MT) * (int)sizeof(float);
    cudaFuncSetAttribute(eval_kernel, cudaFuncAttributeMaxDynamicSharedMemorySize, smem);

    fold_kernel<<<HH*HH/TPB, TPB>>>(W[0], W[1], W[2], W[3]);

    pre_kernel<<<GRID, TPB>>>(x, c, bn1m, bn1v, bn1g, bn1b,
                              Wg[0], bg[0], Wb[0], Wg[1], bg[1], Wb[1],
                              Wg[2], bg[2], Wb[2], Wg[3], bg[3], Wb[3]);

    const float tcs[4] = {0.f, 0.5f, 0.5f, 1.f};
    for (int i = 0; i < 3; ++i) {
        for (int s = 0; s < 4; ++s) {
            eval_kernel<<<GRID, TPB, smem>>>(
                W[0], bb[0], Wg[0], Wb[0],
                W[1], bb[1], Wg[1], Wb[1],
                W[2], bb[2], Wg[2], Wb[2],
                W[3], bb[3], Wg[3], Wb[3],
                sqT, s, (float)i + tcs[s]);
        }
    }

    final_kernel<<<NB, TPB>>>(bn2m, bn2v, bn2g, bn2b, (float*)d_out);
}

// round 4
// speedup vs baseline: 3.2406x; 3.2406x over previous
#include <cuda_runtime.h>
#include <cstdint>

#define P    8192
#define NB   4
#define NPTS 2048
#define Dd   3
#define Cc   64
#define HH   512
#define MT   16
#define TPB  512      // eval kernel
#define PTPB 256      // pre/final kernels
#define GRID (P/MT)
#define EPSBN 1e-4f
#define AS   516      // A smem row stride (floats), bank-conflict-free frags
#define BS   520      // B tile row stride (floats)

// ---------------- scratch (static __device__, no allocations) ----------------
__device__ float g_Gc0[P*HH];
__device__ float g_Gc1[P*HH];
__device__ float g_Gc2[P*HH];
__device__ float g_Gc3[P*Dd];
__device__ float g_Bc0[P*HH];
__device__ float g_Bc1[P*HH];
__device__ float g_Bc2[P*HH];
__device__ float g_Bc3[P*Dd];
__device__ float g_xs[P*Dd];
__device__ float g_xe[P*Dd];
__device__ float g_ax[P*Dd];
__device__ float g_lp[P];
__device__ float g_al[P];

__device__ __forceinline__ float sigf(float z) { return 1.f/(1.f+__expf(-z)); }
__device__ __forceinline__ float htanh(float x) {
    float e = __expf(2.f*x);
    return 1.f - __fdividef(2.f, e + 1.f);
}
__device__ __forceinline__ uint32_t to_tf32(float x) {
    uint32_t r; asm("cvt.rna.tf32.f32 %0, %1;" : "=r"(r) : "f"(x)); return r;
}
__device__ __forceinline__ float tf32r(float x) { return __uint_as_float(to_tf32(x)); }

__device__ __forceinline__ void mma_tf32(float* c,
    uint32_t a0, uint32_t a1, uint32_t a2, uint32_t a3, uint32_t b0, uint32_t b1)
{
    asm volatile("mma.sync.aligned.m16n8k8.row.col.f32.tf32.tf32.f32 "
        "{%0,%1,%2,%3}, {%4,%5,%6,%7}, {%8,%9}, {%0,%1,%2,%3};"
        : "+f"(c[0]), "+f"(c[1]), "+f"(c[2]), "+f"(c[3])
        : "r"(a0), "r"(a1), "r"(a2), "r"(a3), "r"(b0), "r"(b1));
}

// ------------- precompute: bn1, lp init, Gc/Bc = hyper nets applied to c -------------
__global__ void __launch_bounds__(PTPB) pre_kernel(
    const float* __restrict__ x, const float* __restrict__ c,
    const float* __restrict__ m1, const float* __restrict__ v1,
    const float* __restrict__ lg1, const float* __restrict__ be1,
    const float* __restrict__ Wg0, const float* __restrict__ bg0, const float* __restrict__ Wb0,
    const float* __restrict__ Wg1, const float* __restrict__ bg1, const float* __restrict__ Wb1,
    const float* __restrict__ Wg2, const float* __restrict__ bg2, const float* __restrict__ Wb2,
    const float* __restrict__ Wg3, const float* __restrict__ bg3, const float* __restrict__ Wb3)
{
    __shared__ float cs[MT][Cc];
    int tid = threadIdx.x;
    int base = blockIdx.x * MT;
    for (int i = tid; i < MT*Cc; i += PTPB) cs[i>>6][i&63] = c[base*Cc + i];
    if (tid < MT*Dd) {
        int m = tid/Dd, d = tid - m*Dd, p = base+m;
        float val = (x[p*Dd+d] - m1[d]) * __expf(lg1[d]) * rsqrtf(v1[d]+EPSBN) + be1[d];
        g_xs[p*Dd+d] = val; g_xe[p*Dd+d] = val;
    }
    if (tid >= 64 && tid < 64+MT) {
        int m = tid-64, p = base+m;
        float ld = 0.f;
        #pragma unroll
        for (int d = 0; d < Dd; ++d) ld += lg1[d] - 0.5f*logf(v1[d]+EPSBN);
        g_lp[p] = -ld;
    }
    __syncthreads();

    const float* WGs[3] = {Wg0, Wg1, Wg2};
    const float* BGs[3] = {bg0, bg1, bg2};
    const float* WBs[3] = {Wb0, Wb1, Wb2};
    float* GCs[3] = {g_Gc0, g_Gc1, g_Gc2};
    float* BCs[3] = {g_Bc0, g_Bc1, g_Bc2};
    #pragma unroll
    for (int l = 0; l < 3; ++l) {
        const float* Wg = WGs[l]; const float* Wb = WBs[l];
        #pragma unroll
        for (int s = 0; s < 2; ++s) {
            int j = tid + s*PTPB;
            float ag[MT], ab[MT];
            #pragma unroll
            for (int m = 0; m < MT; ++m) { ag[m]=0.f; ab[m]=0.f; }
            const float* wgr = Wg + j*(Cc+1) + 1;
            const float* wbr = Wb + j*(Cc+1) + 1;
            for (int q = 0; q < Cc; ++q) {
                float a = wgr[q], b = wbr[q];
                #pragma unroll
                for (int m = 0; m < MT; ++m) { ag[m] += a*cs[m][q]; ab[m] += b*cs[m][q]; }
            }
            float bgj = BGs[l][j];
            float* Gc = GCs[l]; float* Bc = BCs[l];
            for (int m = 0; m < MT; ++m) {
                int p = base+m;
                Gc[p*HH+j] = ag[m]+bgj; Bc[p*HH+j] = ab[m];
            }
        }
    }
    if (tid < Dd) {
        int j = tid;
        float ag[MT], ab[MT];
        #pragma unroll
        for (int m = 0; m < MT; ++m) { ag[m]=0.f; ab[m]=0.f; }
        const float* wgr = Wg3 + j*(Cc+1) + 1;
        const float* wbr = Wb3 + j*(Cc+1) + 1;
        for (int q = 0; q < Cc; ++q) {
            float a = wgr[q], b = wbr[q];
            #pragma unroll
            for (int m = 0; m < MT; ++m) { ag[m] += a*cs[m][q]; ab[m] += b*cs[m][q]; }
        }
        for (int m = 0; m < MT; ++m) {
            int p = base+m;
            g_Gc3[p*Dd+j] = ag[m]+bg3[j]; g_Bc3[p*Dd+j] = ab[m];
        }
    }
}

// ------------- tf32 tensor-core GEMM: C[64x512] = A[64x512] @ W^T, W row-major [512][512] -------------
// 16 warps, warp w owns cols 32w..32w+31 (4 n-tiles of 8), all 64 rows (4 m-tiles of 16).
// B tile per chunk: FULL 512 n-rows x 16 k, staged by 512 threads x 4 row-groups.
__device__ __forceinline__ void gemm_tc(const float* __restrict__ W,
                                        const float* __restrict__ Asm,
                                        float* __restrict__ Bst,
                                        float c[4][4][4], int tid)
{
    const int warp = tid>>5, lane = tid&31;
    const int g = lane>>2, tq = lane&3;
    const int nbase = warp*32;
    const int srow = tid>>2, skp = tid&3;   // staging: base W row, 16B part within k16
    const float* wbase = W + (size_t)srow*HH + skp*4;

    // stage chunk 0 into buffer 0 (k-major [16][BS], tf32-rounded)
    #pragma unroll
    for (int r = 0; r < 4; ++r) {
        float4 st = *(const float4*)(wbase + (size_t)r*128*HH);
        int n = srow + 128*r;
        Bst[(skp*4+0)*BS + n] = tf32r(st.x);
        Bst[(skp*4+1)*BS + n] = tf32r(st.y);
        Bst[(skp*4+2)*BS + n] = tf32r(st.z);
        Bst[(skp*4+3)*BS + n] = tf32r(st.w);
    }
    __syncthreads();

    for (int kc = 0; kc < 32; ++kc) {
        float4 nx0, nx1, nx2, nx3;
        if (kc < 31) {
            const float* wp = wbase + (kc+1)*16;
            nx0 = *(const float4*)(wp);
            nx1 = *(const float4*)(wp + (size_t)128*HH);
            nx2 = *(const float4*)(wp + (size_t)256*HH);
            nx3 = *(const float4*)(wp + (size_t)384*HH);
        }
        const float* Bt = Bst + (kc&1)*(16*BS);
        #pragma unroll
        for (int ks = 0; ks < 16; ks += 8) {
            const int k0 = kc*16 + ks;
            uint32_t a[4][4];
            #pragma unroll
            for (int mt = 0; mt < 4; ++mt) {
                const float* ap = Asm + (mt*16)*AS + k0;
                a[mt][0] = __float_as_uint(ap[g*AS     + tq]);
                a[mt][1] = __float_as_uint(ap[(g+8)*AS + tq]);
                a[mt][2] = __float_as_uint(ap[g*AS     + tq+4]);
                a[mt][3] = __float_as_uint(ap[(g+8)*AS + tq+4]);
            }
            #pragma unroll
            for (int nt = 0; nt < 4; ++nt) {
                uint32_t b0 = __float_as_uint(Bt[(ks+tq)*BS   + nbase + nt*8 + g]);
                uint32_t b1 = __float_as_uint(Bt[(ks+tq+4)*BS + nbase + nt*8 + g]);
                #pragma unroll
                for (int mt = 0; mt < 4; ++mt)
                    mma_tf32(c[mt][nt], a[mt][0], a[mt][1], a[mt][2], a[mt][3], b0, b1);
            }
        }
        __syncthreads();
        if (kc < 31) {
            float* B1 = Bst + ((kc+1)&1)*(16*BS);
            int n0 = srow;
            B1[(skp*4+0)*BS + n0] = tf32r(nx0.x);
            B1[(skp*4+1)*BS + n0] = tf32r(nx0.y);
            B1[(skp*4+2)*BS + n0] = tf32r(nx0.z);
            B1[(skp*4+3)*BS + n0] = tf32r(nx0.w);
            int n1 = srow + 128;
            B1[(skp*4+0)*BS + n1] = tf32r(nx1.x);
            B1[(skp*4+1)*BS + n1] = tf32r(nx1.y);
            B1[(skp*4+2)*BS + n1] = tf32r(nx1.z);
            B1[(skp*4+3)*BS + n1] = tf32r(nx1.w);
            int n2 = srow + 256;
            B1[(skp*4+0)*BS + n2] = tf32r(nx2.x);
            B1[(skp*4+1)*BS + n2] = tf32r(nx2.y);
            B1[(skp*4+2)*BS + n2] = tf32r(nx2.z);
            B1[(skp*4+3)*BS + n2] = tf32r(nx2.w);
            int n3 = srow + 384;
            B1[(skp*4+0)*BS + n3] = tf32r(nx3.x);
            B1[(skp*4+1)*BS + n3] = tf32r(nx3.y);
            B1[(skp*4+2)*BS + n3] = tf32r(nx3.z);
            B1[(skp*4+3)*BS + n3] = tf32r(nx3.w);
            __syncthreads();
        }
    }
}

// scatter C fragments into A buffer (raw fp32)
__device__ __forceinline__ void scatter_c(float* __restrict__ Asm, float c[4][4][4], int tid)
{
    const int warp = tid>>5, lane = tid&31;
    const int g = lane>>2, tq = lane&3;
    const int nbase = warp*32;
    #pragma unroll
    for (int mt = 0; mt < 4; ++mt)
        #pragma unroll
        for (int nt = 0; nt < 4; ++nt) {
            int col = nbase + nt*8 + 2*tq;
            *(float2*)(Asm + (mt*16+g)*AS + col)   = make_float2(c[mt][nt][0], c[mt][nt][1]);
            *(float2*)(Asm + (mt*16+g+8)*AS + col) = make_float2(c[mt][nt][2], c[mt][nt][3]);
        }
}

// ------------- one dynamics eval (primal + 3 JVPs fused in 64-row GEMMs) + RK4 stage -------------
__global__ void __launch_bounds__(TPB) eval_kernel(
    const float* __restrict__ W0, const float* __restrict__ b0,
    const float* __restrict__ Wg0, const float* __restrict__ Wb0,
    const float* __restrict__ W1, const float* __restrict__ b1,
    const float* __restrict__ Wg1, const float* __restrict__ Wb1,
    const float* __restrict__ W2, const float* __restrict__ b2,
    const float* __restrict__ Wg2, const float* __restrict__ Wb2,
    const float* __restrict__ W3, const float* __restrict__ b3,
    const float* __restrict__ Wg3, const float* __restrict__ Wb3,
    const float* __restrict__ sqrtT, int stage, float tc)
{
    extern __shared__ float sm[];
    float* A    = sm;                    // 64*AS
    float* Bst  = A + 64*AS;             // 2*16*BS
    float* wred = Bst + 2*16*BS;         // 16 warps * 96
    float* xin  = wred + 16*96;          // 48
    float* sdx  = xin + MT*Dd;           // 48
    float* pdg  = sdx + MT*Dd;           // 48

    const int tid = threadIdx.x;
    const int j = tid;
    const int base = blockIdx.x*MT;
    const float sT = sqrtT[0];
    const float dt = sT*sT*(1.f/3.f);
    const float t  = tc*dt;

    if (tid < MT*Dd) xin[tid] = g_xe[base*Dd + tid];
    __syncthreads();

    // ---- L0: rows 0..15 = h1 ; rows 16+16d+m = q1*W0[:,d] ----
    {
        float wa = W0[j*3], wb = W0[j*3+1], wc = W0[j*3+2];
        float bj = b0[j], wgt = Wg0[j*65], wbt = Wb0[j*65];
        #pragma unroll 4
        for (int m = 0; m < MT; ++m) {
            size_t off = (size_t)(base+m)*HH + j;
            float z = xin[m*3]*wa + xin[m*3+1]*wb + xin[m*3+2]*wc + bj;
            float g = sigf(t*wgt + g_Gc0[off]);
            float hv = htanh(z*g + t*wbt + g_Bc0[off]);
            float q = (1.f - hv*hv)*g;
            A[m*AS + j]      = tf32r(hv);
            A[(16+m)*AS + j] = tf32r(q*wa);
            A[(32+m)*AS + j] = tf32r(q*wb);
            A[(48+m)*AS + j] = tf32r(q*wc);
        }
    }
    __syncthreads();

    // ---- GEMM1: [h1; U] @ W1^T ----
    float c[4][4][4];
    #pragma unroll
    for (int a1=0;a1<4;++a1) for (int a2=0;a2<4;++a2) for (int a3=0;a3<4;++a3) c[a1][a2][a3]=0.f;
    gemm_tc(W1, A, Bst, c, tid);
    __syncthreads();
    scatter_c(A, c, tid);
    __syncthreads();

    // ---- EW1 ----
    {
        float bj = b1[j], wgt = Wg1[j*65], wbt = Wb1[j*65];
        #pragma unroll 4
        for (int m = 0; m < MT; ++m) {
            size_t off = (size_t)(base+m)*HH + j;
            float z = A[m*AS + j] + bj;
            float g = sigf(t*wgt + g_Gc1[off]);
            float hv = htanh(z*g + t*wbt + g_Bc1[off]);
            float q = (1.f - hv*hv)*g;
            A[m*AS + j] = tf32r(hv);
            #pragma unroll
            for (int d = 0; d < 3; ++d) {
                int r = 16 + 16*d + m;
                A[r*AS + j] = tf32r(q * A[r*AS + j]);
            }
        }
    }
    __syncthreads();

    // ---- GEMM2: [h2; ub] @ W2^T ----
    #pragma unroll
    for (int a1=0;a1<4;++a1) for (int a2=0;a2<4;++a2) for (int a3=0;a3<4;++a3) c[a1][a2][a3]=0.f;
    gemm_tc(W2, A, Bst, c, tid);
    __syncthreads();
    scatter_c(A, c, tid);
    __syncthreads();

    // ---- EW2 + warp reductions of dx and gated tangent dot ----
    {
        const int warp = tid>>5;
        float bj = b2[j], wgt = Wg2[j*65], wbt = Wb2[j*65];
        float w3d[3];
        #pragma unroll
        for (int d = 0; d < 3; ++d) w3d[d] = W3[d*HH + j];
        for (int m = 0; m < MT; ++m) {
            size_t off = (size_t)(base+m)*HH + j;
            float z = A[m*AS + j] + bj;
            float g = sigf(t*wgt + g_Gc2[off]);
            float hv = htanh(z*g + t*wbt + g_Bc2[off]);
            float q = (1.f - hv*hv)*g;
            float v[6];
            #pragma unroll
            for (int d = 0; d < 3; ++d) {
                v[d]   = hv * w3d[d];
                v[3+d] = q * w3d[d] * A[(16+16*d+m)*AS + j];
            }
            #pragma unroll
            for (int k = 0; k < 6; ++k) {
                float s = v[k];
                #pragma unroll
                for (int o = 16; o > 0; o >>= 1) s += __shfl_xor_sync(0xffffffffu, s, o);
                v[k] = s;
            }
            if ((tid&31) == 0) {
                #pragma unroll
                for (int k = 0; k < 6; ++k) wred[warp*96 + m*6 + k] = v[k];
            }
        }
    }
    __syncthreads();

    // ---- combine across 16 warps; apply output gate/bias ----
    if (tid < 96) {
        int m = tid/6, k = tid - m*6;
        float s = 0.f;
        #pragma unroll
        for (int w = 0; w < 16; ++w) s += wred[w*96 + tid];
        int p = base + m;
        if (k < 3) {
            int d = k;
            float g3 = sigf(t*Wg3[d*65] + g_Gc3[p*3+d]);
            sdx[m*3+d] = (s + b3[d])*g3 + t*Wb3[d*65] + g_Bc3[p*3+d];
        } else {
            int d = k-3;
            float g3 = sigf(t*Wg3[d*65] + g_Gc3[p*3+d]);
            pdg[m*3+d] = s*g3;
        }
    }
    __syncthreads();

    // ---- fused RK4 stage update ----
    if (tid < MT) {
        int m = tid, p = base+m;
        float kl = -(pdg[m*3] + pdg[m*3+1] + pdg[m*3+2]);
        float kx0 = sdx[m*3], kx1 = sdx[m*3+1], kx2 = sdx[m*3+2];
        if (stage == 0) {
            g_al[p] = kl;
            g_ax[p*3]=kx0; g_ax[p*3+1]=kx1; g_ax[p*3+2]=kx2;
            g_xe[p*3]  = g_xs[p*3]  + 0.5f*dt*kx0;
            g_xe[p*3+1]= g_xs[p*3+1]+ 0.5f*dt*kx1;
            g_xe[p*3+2]= g_xs[p*3+2]+ 0.5f*dt*kx2;
        } else if (stage == 1) {
            g_al[p] += 2.f*kl;
            g_ax[p*3]+=2.f*kx0; g_ax[p*3+1]+=2.f*kx1; g_ax[p*3+2]+=2.f*kx2;
            g_xe[p*3]  = g_xs[p*3]  + 0.5f*dt*kx0;
            g_xe[p*3+1]= g_xs[p*3+1]+ 0.5f*dt*kx1;
            g_xe[p*3+2]= g_xs[p*3+2]+ 0.5f*dt*kx2;
        } else if (stage == 2) {
            g_al[p] += 2.f*kl;
            g_ax[p*3]+=2.f*kx0; g_ax[p*3+1]+=2.f*kx1; g_ax[p*3+2]+=2.f*kx2;
            g_xe[p*3]  = g_xs[p*3]  + dt*kx0;
            g_xe[p*3+1]= g_xs[p*3+1]+ dt*kx1;
            g_xe[p*3+2]= g_xs[p*3+2]+ dt*kx2;
        } else {
            float c6 = dt*(1.f/6.f);
            g_lp[p] += c6*(g_al[p] + kl);
            float n0 = g_xs[p*3]   + c6*(g_ax[p*3]   + kx0);
            float n1 = g_xs[p*3+1] + c6*(g_ax[p*3+1] + kx1);
            float n2 = g_xs[p*3+2] + c6*(g_ax[p*3+2] + kx2);
            g_xs[p*3]=n0;   g_xe[p*3]=n0;
            g_xs[p*3+1]=n1; g_xe[p*3+1]=n1;
            g_xs[p*3+2]=n2; g_xe[p*3+2]=n2;
        }
    }
}

// ------------- bn2 + per-batch logp reduction + output -------------
__global__ void __launch_bounds__(PTPB) final_kernel(
    const float* __restrict__ m2, const float* __restrict__ v2,
    const float* __restrict__ lg2, const float* __restrict__ be2,
    float* __restrict__ out)
{
    __shared__ float red[PTPB];
    int b = blockIdx.x, tid = threadIdx.x;
    float sc[3], mn[3], bt[3];
    float ld2 = 0.f;
    #pragma unroll
    for (int d = 0; d < 3; ++d) {
        sc[d] = __expf(lg2[d]) * rsqrtf(v2[d]+EPSBN);
        mn[d] = m2[d]; bt[d] = be2[d];
        ld2 += lg2[d] - 0.5f*logf(v2[d]+EPSBN);
    }
    float part = 0.f;
    for (int n = tid; n < NPTS; n += PTPB) {
        int p = b*NPTS + n;
        #pragma unroll
        for (int d = 0; d < 3; ++d)
            out[p*3+d] = (g_xs[p*3+d]-mn[d])*sc[d] + bt[d];
        part += g_lp[p] - ld2;
    }
    red[tid] = part;
    __syncthreads();
    for (int off = PTPB/2; off > 0; off >>= 1) {
        if (tid < off) red[tid] += red[tid+off];
        __syncthreads();
    }
    if (tid == 0) out[P*3 + b] = red[0];
}

// ---------------- launch ----------------
extern "C" void kernel_launch(void* const* d_in, const int* in_sizes, int n_in,
                              void* d_out, int out_size)
{
    const float* x    = (const float*)d_in[0];
    const float* c    = (const float*)d_in[1];
    const float* bn1m = (const float*)d_in[2];
    const float* bn1v = (const float*)d_in[3];
    const float* bn1g = (const float*)d_in[4];
    const float* bn1b = (const float*)d_in[5];
    const float* bn2m = (const float*)d_in[6];
    const float* bn2v = (const float*)d_in[7];
    const float* bn2g = (const float*)d_in[8];
    const float* bn2b = (const float*)d_in[9];
    const float* sqT  = (const float*)d_in[10];
    const float *W[4], *bb[4], *Wg[4], *bg[4], *Wb[4];
    for (int i = 0; i < 4; ++i) {
        W[i]  = (const float*)d_in[11+5*i];
        bb[i] = (const float*)d_in[12+5*i];
        Wg[i] = (const float*)d_in[13+5*i];
        bg[i] = (const float*)d_in[14+5*i];
        Wb[i] = (const float*)d_in[15+5*i];
    }

    int smem = (64*AS + 2*16*BS + 16*96 + 3*MT*Dd) * (int)sizeof(float);
    cudaFuncSetAttribute(eval_kernel, cudaFuncAttributeMaxDynamicSharedMemorySize, smem);

    pre_kernel<<<GRID, PTPB>>>(x, c, bn1m, bn1v, bn1g, bn1b,
                               Wg[0], bg[0], Wb[0], Wg[1], bg[1], Wb[1],
                               Wg[2], bg[2], Wb[2], Wg[3], bg[3], Wb[3]);

    const float tcs[4] = {0.f, 0.5f, 0.5f, 1.f};
    for (int i = 0; i < 3; ++i) {
        for (int s = 0; s < 4; ++s) {
            eval_kernel<<<GRID, TPB, smem>>>(
                W[0], bb[0], Wg[0], Wb[0],
                W[1], bb[1], Wg[1], Wb[1],
                W[2], bb[2], Wg[2], Wb[2],
                W[3], bb[3], Wg[3], Wb[3],
                sqT, s, (float)i + tcs[s]);
        }
    }

    final_kernel<<<NB, PTPB>>>(bn2m, bn2v, bn2g, bn2b, (float*)d_out);
}

// round 6
// speedup vs baseline: 9.0379x; 2.7889x over previous
#include <cuda_runtime.h>
#include <cuda_fp16.h>
#include <cstdint>

#define P    8192
#define NB   4
#define NPTS 2048
#define Dd   3
#define Cc   64
#define HH   512
#define MT   16
#define TPB  512
#define PTPB 256
#define GRID (P/MT)
#define EPSBN 1e-4f
#define ASH  520            // A smem row stride (halves); 1040B, 16B-aligned, conflict-free
#define BSH  40             // B smem row stride (halves); 80B, 16B-aligned, conflict-free
#define BUFH (512*BSH)      // one B buffer in halves

// ---------------- scratch (static __device__, no allocations) ----------------
__device__ float g_Gc0[P*HH];
__device__ float g_Gc1[P*HH];
__device__ float g_Gc2[P*HH];
__device__ float g_Gc3[P*Dd];
__device__ float g_Bc0[P*HH];
__device__ float g_Bc1[P*HH];
__device__ float g_Bc2[P*HH];
__device__ float g_Bc3[P*Dd];
__device__ float g_xs[P*Dd];
__device__ float g_lp[P];
__device__ __half g_W1h[HH*HH];
__device__ __half g_W2h[HH*HH];

__device__ __forceinline__ float sigf(float z) { return 1.f/(1.f+__expf(-z)); }
__device__ __forceinline__ float htanh(float x) {
    float e = __expf(2.f*x);
    return 1.f - __fdividef(2.f, e + 1.f);
}

#define LDSM4(R0,R1,R2,R3,ADDR) \
    asm volatile("ldmatrix.sync.aligned.m8n8.x4.shared.b16 {%0,%1,%2,%3}, [%4];" \
        : "=r"(R0),"=r"(R1),"=r"(R2),"=r"(R3) : "r"(ADDR))
#define CPA(DST,SRC) asm volatile("cp.async.cg.shared.global [%0], [%1], 16;" ::"r"(DST),"l"(SRC))
#define CPC()        asm volatile("cp.async.commit_group;")
#define CPW1()       asm volatile("cp.async.wait_group 1;")

__device__ __forceinline__ void mma_f16(float* c,
    uint32_t a0, uint32_t a1, uint32_t a2, uint32_t a3, uint32_t b0, uint32_t b1)
{
    asm volatile("mma.sync.aligned.m16n8k16.row.col.f32.f16.f16.f32 "
        "{%0,%1,%2,%3}, {%4,%5,%6,%7}, {%8,%9}, {%0,%1,%2,%3};"
        : "+f"(c[0]), "+f"(c[1]), "+f"(c[2]), "+f"(c[3])
        : "r"(a0), "r"(a1), "r"(a2), "r"(a3), "r"(b0), "r"(b1));
}

// ------------- weight fp16 conversion (once per launch) -------------
__global__ void __launch_bounds__(TPB) conv_kernel(const float* __restrict__ W1,
                                                   const float* __restrict__ W2)
{
    int idx = blockIdx.x*TPB + threadIdx.x;
    g_W1h[idx] = __float2half_rn(W1[idx]);
    g_W2h[idx] = __float2half_rn(W2[idx]);
}

// ------------- precompute: bn1, lp init, Gc/Bc = hyper nets applied to c -------------
__global__ void __launch_bounds__(PTPB) pre_kernel(
    const float* __restrict__ x, const float* __restrict__ c,
    const float* __restrict__ m1, const float* __restrict__ v1,
    const float* __restrict__ lg1, const float* __restrict__ be1,
    const float* __restrict__ Wg0, const float* __restrict__ bg0, const float* __restrict__ Wb0,
    const float* __restrict__ Wg1, const float* __restrict__ bg1, const float* __restrict__ Wb1,
    const float* __restrict__ Wg2, const float* __restrict__ bg2, const float* __restrict__ Wb2,
    const float* __restrict__ Wg3, const float* __restrict__ bg3, const float* __restrict__ Wb3)
{
    __shared__ float cs[MT][Cc];
    int tid = threadIdx.x;
    int base = blockIdx.x * MT;
    for (int i = tid; i < MT*Cc; i += PTPB) cs[i>>6][i&63] = c[base*Cc + i];
    if (tid < MT*Dd) {
        int m = tid/Dd, d = tid - m*Dd, p = base+m;
        g_xs[p*Dd+d] = (x[p*Dd+d] - m1[d]) * __expf(lg1[d]) * rsqrtf(v1[d]+EPSBN) + be1[d];
    }
    if (tid >= 64 && tid < 64+MT) {
        int m = tid-64, p = base+m;
        float ld = 0.f;
        #pragma unroll
        for (int d = 0; d < Dd; ++d) ld += lg1[d] - 0.5f*logf(v1[d]+EPSBN);
        g_lp[p] = -ld;
    }
    __syncthreads();

    const float* WGs[3] = {Wg0, Wg1, Wg2};
    const float* BGs[3] = {bg0, bg1, bg2};
    const float* WBs[3] = {Wb0, Wb1, Wb2};
    float* GCs[3] = {g_Gc0, g_Gc1, g_Gc2};
    float* BCs[3] = {g_Bc0, g_Bc1, g_Bc2};
    #pragma unroll
    for (int l = 0; l < 3; ++l) {
        const float* Wg = WGs[l]; const float* Wb = WBs[l];
        #pragma unroll
        for (int s = 0; s < 2; ++s) {
            int j = tid + s*PTPB;
            float ag[MT], ab[MT];
            #pragma unroll
            for (int m = 0; m < MT; ++m) { ag[m]=0.f; ab[m]=0.f; }
            const float* wgr = Wg + j*(Cc+1) + 1;
            const float* wbr = Wb + j*(Cc+1) + 1;
            for (int q = 0; q < Cc; ++q) {
                float a = wgr[q], b = wbr[q];
                #pragma unroll
                for (int m = 0; m < MT; ++m) { ag[m] += a*cs[m][q]; ab[m] += b*cs[m][q]; }
            }
            float bgj = BGs[l][j];
            float* Gc = GCs[l]; float* Bc = BCs[l];
            for (int m = 0; m < MT; ++m) {
                int p = base+m;
                Gc[p*HH+j] = ag[m]+bgj; Bc[p*HH+j] = ab[m];
            }
        }
    }
    if (tid < Dd) {
        int j = tid;
        float ag[MT], ab[MT];
        #pragma unroll
        for (int m = 0; m < MT; ++m) { ag[m]=0.f; ab[m]=0.f; }
        const float* wgr = Wg3 + j*(Cc+1) + 1;
        const float* wbr = Wb3 + j*(Cc+1) + 1;
        for (int q = 0; q < Cc; ++q) {
            float a = wgr[q], b = wbr[q];
            #pragma unroll
            for (int m = 0; m < MT; ++m) { ag[m] += a*cs[m][q]; ab[m] += b*cs[m][q]; }
        }
        for (int m = 0; m < MT; ++m) {
            int p = base+m;
            g_Gc3[p*Dd+j] = ag[m]+bg3[j]; g_Bc3[p*Dd+j] = ab[m];
        }
    }
}

// ------------- fp16 TC GEMM: C[64x512] = A[64x512] @ W^T, cp.async 3-stage pipeline -------------
__device__ __forceinline__ void stage_chunk(const __half* __restrict__ Wh,
                                            uint32_t bB, int buf, int kc,
                                            int srow, int q)
{
    const __half* src = Wh + (size_t)srow*HH + kc*32 + q*8;
    uint32_t dst = bB + (uint32_t)buf*BUFH*2 + (srow*BSH + q*8)*2;
    #pragma unroll
    for (int r = 0; r < 4; ++r)
        CPA(dst + r*128*BSH*2, src + (size_t)r*128*HH);
}

__device__ __forceinline__ void gemm_f16(const __half* __restrict__ Wh,
                                         uint32_t aB, uint32_t bB,
                                         float c[4][4][4], int tid)
{
    const int warp = tid>>5, lane = tid&31;
    const int arow = lane & 15, acolo = (lane>>4)*8;
    const int bno  = (lane&7) + ((lane>>4)<<3);
    const int bcolo = lane & 8;
    const int q = tid & 3, srow = tid >> 2;

    stage_chunk(Wh, bB, 0, 0, srow, q); CPC();
    stage_chunk(Wh, bB, 1, 1, srow, q); CPC();

    for (int kc = 0; kc < 16; ++kc) {
        CPW1();
        __syncthreads();
        if (kc+2 < 16) stage_chunk(Wh, bB, (kc+2)%3, kc+2, srow, q);
        CPC();

        uint32_t bbuf = bB + (uint32_t)(kc%3)*BUFH*2;
        #pragma unroll
        for (int ks = 0; ks < 32; ks += 16) {
            uint32_t a[4][4], b[2][4];
            #pragma unroll
            for (int mt = 0; mt < 4; ++mt) {
                uint32_t addr = aB + (uint32_t)(((mt*16+arow)*ASH) + kc*32 + ks + acolo)*2;
                LDSM4(a[mt][0], a[mt][1], a[mt][2], a[mt][3], addr);
            }
            #pragma unroll
            for (int np = 0; np < 2; ++np) {
                uint32_t addr = bbuf + (uint32_t)(((warp*32 + np*16 + bno)*BSH) + ks + bcolo)*2;
                LDSM4(b[np][0], b[np][1], b[np][2], b[np][3], addr);
            }
            #pragma unroll
            for (int np = 0; np < 2; ++np)
                #pragma unroll
                for (int ntl = 0; ntl < 2; ++ntl)
                    #pragma unroll
                    for (int mt = 0; mt < 4; ++mt)
                        mma_f16(c[mt][np*2+ntl], a[mt][0], a[mt][1], a[mt][2], a[mt][3],
                                b[np][ntl*2], b[np][ntl*2+1]);
        }
    }
}

__device__ __forceinline__ void scatter_f16(__half* __restrict__ Ah, float c[4][4][4], int tid)
{
    const int warp = tid>>5, lane = tid&31;
    const int g = lane>>2, tq = lane&3;
    const int nb = warp*32;
    #pragma unroll
    for (int mt = 0; mt < 4; ++mt)
        #pragma unroll
        for (int nt = 0; nt < 4; ++nt) {
            int col = nb + nt*8 + 2*tq;
            *(__half2*)(Ah + (mt*16+g)*ASH + col)   = __floats2half2_rn(c[mt][nt][0], c[mt][nt][1]);
            *(__half2*)(Ah + (mt*16+g+8)*ASH + col) = __floats2half2_rn(c[mt][nt][2], c[mt][nt][3]);
        }
}

// ------------- persistent flow kernel: all 3 RK4 steps x 4 stages -------------
__global__ void __launch_bounds__(TPB, 1) flow_kernel(
    const float* __restrict__ W0, const float* __restrict__ b0,
    const float* __restrict__ Wg0, const float* __restrict__ Wb0,
    const float* __restrict__ b1,
    const float* __restrict__ Wg1, const float* __restrict__ Wb1,
    const float* __restrict__ b2,
    const float* __restrict__ Wg2, const float* __restrict__ Wb2,
    const float* __restrict__ W3, const float* __restrict__ b3,
    const float* __restrict__ Wg3, const float* __restrict__ Wb3,
    const float* __restrict__ sqrtT)
{
    extern __shared__ char smraw[];
    __half* Ah  = (__half*)smraw;            // 64*ASH halves
    __half* Bh  = Ah + 64*ASH;               // 3*BUFH halves
    float* wred = (float*)(Bh + 3*BUFH);     // 16*96
    float* xin  = wred + 16*96;              // 48
    float* sdx  = xin + 48;                  // 48
    float* pdg  = sdx + 48;                  // 48
    float* xs_s = pdg + 48;                  // 48
    float* ax_s = xs_s + 48;                 // 48
    float* lp_s = ax_s + 48;                 // 16
    float* al_s = lp_s + 16;                 // 16

    const int tid = threadIdx.x;
    const int j = tid;
    const int base = blockIdx.x*MT;
    const uint32_t aB = (uint32_t)__cvta_generic_to_shared(Ah);
    const uint32_t bB = (uint32_t)__cvta_generic_to_shared(Bh);
    const float sT = sqrtT[0];
    const float dt = sT*sT*(1.f/3.f);

    if (tid < 48) { float v = g_xs[base*Dd + tid]; xin[tid] = v; xs_s[tid] = v; }
    if (tid < MT) lp_s[tid] = g_lp[base + tid];
    __syncthreads();

    for (int it = 0; it < 12; ++it) {
        const int s = it & 3;
        const float tc = (s == 0) ? 0.f : ((s == 3) ? 1.f : 0.5f);
        const float t = ((float)(it >> 2) + tc) * dt;

        // ---- L0: rows 0..15 = h1 ; rows 16+16d+m = q1*W0[:,d] ----
        {
            float wa = W0[j*3], wb = W0[j*3+1], wc = W0[j*3+2];
            float bj = b0[j], wgt = Wg0[j*65], wbt = Wb0[j*65];
            #pragma unroll 4
            for (int m = 0; m < MT; ++m) {
                size_t off = (size_t)(base+m)*HH + j;
                float z = xin[m*3]*wa + xin[m*3+1]*wb + xin[m*3+2]*wc + bj;
                float g = sigf(t*wgt + g_Gc0[off]);
                float hv = htanh(z*g + t*wbt + g_Bc0[off]);
                float qq = (1.f - hv*hv)*g;
                Ah[m*ASH + j]      = __float2half_rn(hv);
                Ah[(16+m)*ASH + j] = __float2half_rn(qq*wa);
                Ah[(32+m)*ASH + j] = __float2half_rn(qq*wb);
                Ah[(48+m)*ASH + j] = __float2half_rn(qq*wc);
            }
        }
        // (GEMM1's first internal barrier orders L0 writes before frag reads)

        float c[4][4][4];
        #pragma unroll
        for (int a1=0;a1<4;++a1) for (int a2=0;a2<4;++a2) for (int a3=0;a3<4;++a3) c[a1][a2][a3]=0.f;
        gemm_f16(g_W1h, aB, bB, c, tid);
        __syncthreads();
        scatter_f16(Ah, c, tid);
        __syncthreads();

        // ---- EW1 ----
        {
            float bj = b1[j], wgt = Wg1[j*65], wbt = Wb1[j*65];
            #pragma unroll 4
            for (int m = 0; m < MT; ++m) {
                size_t off = (size_t)(base+m)*HH + j;
                float z = __half2float(Ah[m*ASH + j]) + bj;
                float g = sigf(t*wgt + g_Gc1[off]);
                float hv = htanh(z*g + t*wbt + g_Bc1[off]);
                float qq = (1.f - hv*hv)*g;
                Ah[m*ASH + j] = __float2half_rn(hv);
                #pragma unroll
                for (int d = 0; d < 3; ++d) {
                    int r = 16 + 16*d + m;
                    Ah[r*ASH + j] = __float2half_rn(qq * __half2float(Ah[r*ASH + j]));
                }
            }
        }
        // (GEMM2's first internal barrier orders EW1 writes before frag reads)

        #pragma unroll
        for (int a1=0;a1<4;++a1) for (int a2=0;a2<4;++a2) for (int a3=0;a3<4;++a3) c[a1][a2][a3]=0.f;
        gemm_f16(g_W2h, aB, bB, c, tid);
        __syncthreads();
        scatter_f16(Ah, c, tid);
        __syncthreads();

        // ---- EW2 + warp reductions of dx and gated tangent dot ----
        {
            const int warp = tid>>5;
            float bj = b2[j], wgt = Wg2[j*65], wbt = Wb2[j*65];
            float w3d[3];
            #pragma unroll
            for (int d = 0; d < 3; ++d) w3d[d] = W3[d*HH + j];
            for (int m = 0; m < MT; ++m) {
                size_t off = (size_t)(base+m)*HH + j;
                float z = __half2float(Ah[m*ASH + j]) + bj;
                float g = sigf(t*wgt + g_Gc2[off]);
                float hv = htanh(z*g + t*wbt + g_Bc2[off]);
                float qq = (1.f - hv*hv)*g;
                float v[6];
                #pragma unroll
                for (int d = 0; d < 3; ++d) {
                    v[d]   = hv * w3d[d];
                    v[3+d] = qq * w3d[d] * __half2float(Ah[(16+16*d+m)*ASH + j]);
                }
                #pragma unroll
                for (int k = 0; k < 6; ++k) {
                    float sv = v[k];
                    #pragma unroll
                    for (int o = 16; o > 0; o >>= 1) sv += __shfl_xor_sync(0xffffffffu, sv, o);
                    v[k] = sv;
                }
                if ((tid&31) == 0) {
                    #pragma unroll
                    for (int k = 0; k < 6; ++k) wred[warp*96 + m*6 + k] = v[k];
                }
            }
        }
        __syncthreads();

        // ---- combine across 16 warps; apply output gate/bias ----
        if (tid < 96) {
            int m = tid/6, k = tid - m*6;
            float sv = 0.f;
            #pragma unroll
            for (int w = 0; w < 16; ++w) sv += wred[w*96 + tid];
            int p = base + m;
            if (k < 3) {
                int d = k;
                float g3 = sigf(t*Wg3[d*65] + g_Gc3[p*3+d]);
                sdx[m*3+d] = (sv + b3[d])*g3 + t*Wb3[d*65] + g_Bc3[p*3+d];
            } else {
                int d = k-3;
                float g3 = sigf(t*Wg3[d*65] + g_Gc3[p*3+d]);
                pdg[m*3+d] = sv*g3;
            }
        }
        __syncthreads();

        // ---- RK4 stage update (state in smem) ----
        if (tid < MT) {
            int m = tid;
            float kl = -(pdg[m*3] + pdg[m*3+1] + pdg[m*3+2]);
            if (s == 0) {
                al_s[m] = kl;
                #pragma unroll
                for (int d = 0; d < 3; ++d) {
                    float kx = sdx[m*3+d];
                    ax_s[m*3+d] = kx;
                    xin[m*3+d] = xs_s[m*3+d] + 0.5f*dt*kx;
                }
            } else if (s == 1) {
                al_s[m] += 2.f*kl;
                #pragma unroll
                for (int d = 0; d < 3; ++d) {
                    float kx = sdx[m*3+d];
                    ax_s[m*3+d] += 2.f*kx;
                    xin[m*3+d] = xs_s[m*3+d] + 0.5f*dt*kx;
                }
            } else if (s == 2) {
                al_s[m] += 2.f*kl;
                #pragma unroll
                for (int d = 0; d < 3; ++d) {
                    float kx = sdx[m*3+d];
                    ax_s[m*3+d] += 2.f*kx;
                    xin[m*3+d] = xs_s[m*3+d] + dt*kx;
                }
            } else {
                float c6 = dt*(1.f/6.f);
                lp_s[m] += c6*(al_s[m] + kl);
                #pragma unroll
                for (int d = 0; d < 3; ++d) {
                    float nv = xs_s[m*3+d] + c6*(ax_s[m*3+d] + sdx[m*3+d]);
                    xs_s[m*3+d] = nv;
                    xin[m*3+d] = nv;
                }
            }
        }
        __syncthreads();
    }

    if (tid < 48) g_xs[base*Dd + tid] = xs_s[tid];
    if (tid < MT) g_lp[base + tid] = lp_s[tid];
}

// ------------- bn2 + per-batch logp reduction + output -------------
__global__ void __launch_bounds__(PTPB) final_kernel(
    const float* __restrict__ m2, const float* __restrict__ v2,
    const float* __restrict__ lg2, const float* __restrict__ be2,
    float* __restrict__ out)
{
    __shared__ float red[PTPB];
    int b = blockIdx.x, tid = threadIdx.x;
    float sc[3], mn[3], bt[3];
    float ld2 = 0.f;
    #pragma unroll
    for (int d = 0; d < 3; ++d) {
        sc[d] = __expf(lg2[d]) * rsqrtf(v2[d]+EPSBN);
        mn[d] = m2[d]; bt[d] = be2[d];
        ld2 += lg2[d] - 0.5f*logf(v2[d]+EPSBN);
    }
    float part = 0.f;
    for (int n = tid; n < NPTS; n += PTPB) {
        int p = b*NPTS + n;
        #pragma unroll
        for (int d = 0; d < 3; ++d)
            out[p*3+d] = (g_xs[p*3+d]-mn[d])*sc[d] + bt[d];
        part += g_lp[p] - ld2;
    }
    red[tid] = part;
    __syncthreads();
    for (int off = PTPB/2; off > 0; off >>= 1) {
        if (tid < off) red[tid] += red[tid+off];
        __syncthreads();
    }
    if (tid == 0) out[P*3 + b] = red[0];
}

// ---------------- launch ----------------
extern "C" void kernel_launch(void* const* d_in, const int* in_sizes, int n_in,
                              void* d_out, int out_size)
{
    const float* x    = (const float*)d_in[0];
    const float* c    = (const float*)d_in[1];
    const float* bn1m = (const float*)d_in[2];
    const float* bn1v = (const float*)d_in[3];
    const float* bn1g = (const float*)d_in[4];
    const float* bn1b = (const float*)d_in[5];
    const float* bn2m = (const float*)d_in[6];
    const float* bn2v = (const float*)d_in[7];
    const float* bn2g = (const float*)d_in[8];
    const float* bn2b = (const float*)d_in[9];
    const float* sqT  = (const float*)d_in[10];
    const float *W[4], *bb[4], *Wg[4], *bg[4], *Wb[4];
    for (int i = 0; i < 4; ++i) {
        W[i]  = (const float*)d_in[11+5*i];
        bb[i] = (const float*)d_in[12+5*i];
        Wg[i] = (const float*)d_in[13+5*i];
        bg[i] = (const float*)d_in[14+5*i];
        Wb[i] = (const float*)d_in[15+5*i];
    }

    int smem = (64*ASH + 3*BUFH)*2 + (16*96 + 48*5 + 16*2)*4;
    cudaFuncSetAttribute(flow_kernel, cudaFuncAttributeMaxDynamicSharedMemorySize, smem);

    conv_kernel<<<HH*HH/TPB, TPB>>>(W[1], W[2]);
    pre_kernel<<<GRID, PTPB>>>(x, c, bn1m, bn1v, bn1g, bn1b,
                               Wg[0], bg[0], Wb[0], Wg[1], bg[1], Wb[1],
                               Wg[2], bg[2], Wb[2], Wg[3], bg[3], Wb[3]);
    flow_kernel<<<GRID, TPB, smem>>>(
        W[0], bb[0], Wg[0], Wb[0],
        bb[1], Wg[1], Wb[1],
        bb[2], Wg[2], Wb[2],
        W[3], bb[3], Wg[3], Wb[3],
        sqT);
    final_kernel<<<NB, PTPB>>>(bn2m, bn2v, bn2g, bn2b, (float*)d_out);
}